// round 15
// baseline (speedup 1.0000x reference)
#include <cuda_runtime.h>
#include <cuda_bf16.h>
#include <stdint.h>

#define B_  64
#define T_  1024
#define J_  128
#define D_  256
#define TT  128
#define NWARP 16

// strides (bytes)
#define USTB 528     // U row stride: 132 words ≡ 4 mod 32 -> conflict-free ldmatrix
#define HSTB 272     // H/P row stride: 68 words ≡ 4 mod 32

// smem byte offsets
#define SM_SH   0
#define SM_SU   512
#define SM_INV  1024
#define SM_RM   1536                    // [4][128] f32 = 2048
#define SM_RS   3584                    // [4][128] f32 = 2048
#define SM_L    5632                    // L[128] f32 (ends 6144 < 8192)
#define AU_HI   8192
#define AU_LO   (AU_HI + J_*USTB)       // +67584
#define AH_HI   (AU_LO + J_*USTB)
#define AH_LO   (AH_HI + TT*HSTB)       // +34816
#define SMEM_TOTAL (AH_LO + TT*HSTB)    // 213504 B
#define AP_HI   AH_HI                   // P overlays H after GEMM1
#define AP_LO   AH_LO
#define SM_VR   AU_HI                   // V reduce [16][256] f32 = 16384 (U dead)
#define SM_VS   (AU_HI + 16384)         // s_c partials [16] f32
#define SM_Q2C  (AU_HI + 16448)         // q2c[256] f32 (finisher)

__device__ __align__(16) float g_Vp[B_*8*D_];   // per-tile V_c
__device__ __align__(16) float g_Ms[B_*8*2];    // per-tile {M_c, s_c}
__device__ unsigned g_cnt[B_];                  // finisher counters (self-resetting)

// ---------------- helpers ----------------
__device__ __forceinline__ uint32_t smem_u32(const void* p) {
    uint32_t a;
    asm("{ .reg .u64 t; cvta.to.shared.u64 t, %1; cvt.u32.u64 %0, t; }" : "=r"(a) : "l"(p));
    return a;
}
__device__ __forceinline__ void ldsm4(uint32_t* r, uint32_t addr) {
    asm volatile("ldmatrix.sync.aligned.m8n8.x4.shared.b16 {%0,%1,%2,%3}, [%4];"
        : "=r"(r[0]), "=r"(r[1]), "=r"(r[2]), "=r"(r[3]) : "r"(addr));
}
__device__ __forceinline__ void ldsm4t(uint32_t* r, uint32_t addr) {
    asm volatile("ldmatrix.sync.aligned.m8n8.x4.trans.shared.b16 {%0,%1,%2,%3}, [%4];"
        : "=r"(r[0]), "=r"(r[1]), "=r"(r[2]), "=r"(r[3]) : "r"(addr));
}
__device__ __forceinline__ void mma16816(float* c, const uint32_t* a, uint32_t b0, uint32_t b1) {
    asm volatile("mma.sync.aligned.m16n8k16.row.col.f32.bf16.bf16.f32 "
        "{%0,%1,%2,%3}, {%4,%5,%6,%7}, {%8,%9}, {%0,%1,%2,%3};"
        : "+f"(c[0]), "+f"(c[1]), "+f"(c[2]), "+f"(c[3])
        : "r"(a[0]), "r"(a[1]), "r"(a[2]), "r"(a[3]), "r"(b0), "r"(b1));
}
static __device__ __forceinline__ uint32_t pk(float a, float b) {
    return (uint32_t)__bfloat16_as_ushort(__float2bfloat16(a))
         | ((uint32_t)__bfloat16_as_ushort(__float2bfloat16(b)) << 16);
}
static __device__ __forceinline__ float rsd(float x) {
    return x - __bfloat162float(__float2bfloat16(x));
}

// ---------------------------------------------------------------------------
// Single fused kernel. 1 CTA per (b, 128-row t-tile). 16 warps.
// ---------------------------------------------------------------------------
__global__ void __launch_bounds__(512, 1)
bidaf_main(const float* __restrict__ H, const float* __restrict__ U,
           const float* __restrict__ w_h, const float* __restrict__ w_u,
           const float* __restrict__ w_hu, float* __restrict__ G)
{
    extern __shared__ char smem[];
    const uint32_t sb = smem_u32(smem);
    float* shS  = (float*)(smem + SM_SH);
    float* suS  = (float*)(smem + SM_SU);
    float* invS = (float*)(smem + SM_INV);
    float* redM = (float*)(smem + SM_RM);
    float* redS = (float*)(smem + SM_RS);
    float* Lsm  = (float*)(smem + SM_L);
    __shared__ unsigned finOld;

    const int tid  = threadIdx.x;
    const int lane = tid & 31;
    const int warp = tid >> 5;
    const int rg   = warp & 3;
    const int jg   = warp >> 2;       // 0..3 (also dg in GEMM2)
    const int rbase = rg * 32;
    const int b    = blockIdx.y;
    const int tb   = blockIdx.x * TT;

    const int lr = lane & 7;
    const int g  = lane >> 3;
    const uint32_t aoff = (uint32_t)((((g & 1) << 3) + lr) * HSTB + ((g >> 1) << 4));
    const uint32_t boff = (uint32_t)((((g >> 1) << 3) + lr) * USTB + ((g & 1) << 4));
    const uint32_t toff = (uint32_t)((((g & 1) << 3) + lr) * USTB + ((g >> 1) << 4));

    // ---- stage U full-K (hi/lo) + su ----
    {
        const float4* wu4 = (const float4*)w_u;
        float4 wa = wu4[lane], wb = wu4[32 + lane];
#pragma unroll
        for (int it = 0; it < 8; it++) {
            int j = warp + it * NWARP;
            const float4* Uj = (const float4*)(U + (size_t)(b * J_ + j) * D_);
            float4 v0 = Uj[lane], v1 = Uj[32 + lane];
            float s = v0.x*wa.x + v0.y*wa.y + v0.z*wa.z + v0.w*wa.w
                    + v1.x*wb.x + v1.y*wb.y + v1.z*wb.z + v1.w*wb.w;
#pragma unroll
            for (int o = 16; o; o >>= 1) s += __shfl_xor_sync(0xffffffffu, s, o);
            if (lane == 0) suS[j] = s;
            uint32_t ro = (uint32_t)j * USTB + (uint32_t)lane * 8;
            *(uint2*)(smem + AU_HI + ro)       = make_uint2(pk(v0.x,v0.y), pk(v0.z,v0.w));
            *(uint2*)(smem + AU_HI + ro + 256) = make_uint2(pk(v1.x,v1.y), pk(v1.z,v1.w));
            *(uint2*)(smem + AU_LO + ro)       = make_uint2(pk(rsd(v0.x),rsd(v0.y)), pk(rsd(v0.z),rsd(v0.w)));
            *(uint2*)(smem + AU_LO + ro + 256) = make_uint2(pk(rsd(v1.x),rsd(v1.y)), pk(rsd(v1.z),rsd(v1.w)));
        }
    }

    // ---- stage H chunk 0 ----
    {
        const float4* wh4  = (const float4*)w_h;
        const float4* whu4 = (const float4*)w_hu;
        float4 wv = wh4[lane];
        float4 mv = whu4[lane];
#pragma unroll
        for (int it = 0; it < 8; it++) {
            int row = warp + it * NWARP;
            float4 v = ((const float4*)(H + (size_t)(b*T_ + tb + row) * D_))[lane];
            float s = v.x*wv.x + v.y*wv.y + v.z*wv.z + v.w*wv.w;
#pragma unroll
            for (int o = 16; o; o >>= 1) s += __shfl_xor_sync(0xffffffffu, s, o);
            if (lane == 0) shS[row] = s;
            float x0 = v.x*mv.x, x1 = v.y*mv.y, x2 = v.z*mv.z, x3 = v.w*mv.w;
            uint32_t ro = (uint32_t)row * HSTB + (uint32_t)lane * 8;
            *(uint2*)(smem + AH_HI + ro) = make_uint2(pk(x0,x1), pk(x2,x3));
            *(uint2*)(smem + AH_LO + ro) = make_uint2(pk(rsd(x0),rsd(x1)), pk(rsd(x2),rsd(x3)));
        }
    }

    // ---- prefetch H chunk 1 into registers (flies during MMA chunk 0) ----
    float4 pre[8];
#pragma unroll
    for (int it = 0; it < 8; it++) {
        int row = warp + it * NWARP;
        pre[it] = ((const float4*)(H + (size_t)(b*T_ + tb + row) * D_ + 128))[lane];
    }

    float acc[2][4][4];
#pragma unroll
    for (int rt = 0; rt < 2; rt++)
#pragma unroll
        for (int nt = 0; nt < 4; nt++)
#pragma unroll
            for (int c = 0; c < 4; c++) acc[rt][nt][c] = 0.f;

    // ---- GEMM1 over two H k-chunks (32 j per warp) ----
    const uint32_t ahi = sb + AH_HI + aoff + (uint32_t)rbase * HSTB;
    const uint32_t alo = sb + AH_LO + aoff + (uint32_t)rbase * HSTB;
    for (int kc = 0; kc < 2; kc++) {
        __syncthreads();
        if (kc == 1) {   // store prefetched chunk 1 (chunk0 ldmatrix reads done)
            const float4* wh4  = (const float4*)w_h;
            const float4* whu4 = (const float4*)w_hu;
            float4 wv = wh4[32 + lane];
            float4 mv = whu4[32 + lane];
#pragma unroll
            for (int it = 0; it < 8; it++) {
                int row = warp + it * NWARP;
                float4 v = pre[it];
                float s = v.x*wv.x + v.y*wv.y + v.z*wv.z + v.w*wv.w;
#pragma unroll
                for (int o = 16; o; o >>= 1) s += __shfl_xor_sync(0xffffffffu, s, o);
                if (lane == 0) shS[row] += s;
                float x0 = v.x*mv.x, x1 = v.y*mv.y, x2 = v.z*mv.z, x3 = v.w*mv.w;
                uint32_t ro = (uint32_t)row * HSTB + (uint32_t)lane * 8;
                *(uint2*)(smem + AH_HI + ro) = make_uint2(pk(x0,x1), pk(x2,x3));
                *(uint2*)(smem + AH_LO + ro) = make_uint2(pk(rsd(x0),rsd(x1)), pk(rsd(x2),rsd(x3)));
            }
            __syncthreads();
        }

        const uint32_t bhiB = sb + AU_HI + boff + (uint32_t)(kc * 256);
        const uint32_t bloB = sb + AU_LO + boff + (uint32_t)(kc * 256);
#pragma unroll 2
        for (int ksl = 0; ksl < 8; ksl++) {
            uint32_t ak = (uint32_t)ksl * 32;
            uint32_t ah0[4], ah1[4], al0[4], al1[4];
            ldsm4(ah0, ahi + ak);
            ldsm4(ah1, ahi + ak + 16u*HSTB);
            ldsm4(al0, alo + ak);
            ldsm4(al1, alo + ak + 16u*HSTB);
#pragma unroll
            for (int nt2 = 0; nt2 < 2; nt2++) {
                uint32_t jb = (uint32_t)(jg*32 + nt2*16) * USTB + ak;
                uint32_t bh[4], bl[4];
                ldsm4(bh, bhiB + jb);
                mma16816(acc[0][2*nt2],   ah0, bh[0], bh[1]);
                mma16816(acc[0][2*nt2+1], ah0, bh[2], bh[3]);
                mma16816(acc[1][2*nt2],   ah1, bh[0], bh[1]);
                mma16816(acc[1][2*nt2+1], ah1, bh[2], bh[3]);
                mma16816(acc[0][2*nt2],   al0, bh[0], bh[1]);
                mma16816(acc[0][2*nt2+1], al0, bh[2], bh[3]);
                mma16816(acc[1][2*nt2],   al1, bh[0], bh[1]);
                mma16816(acc[1][2*nt2+1], al1, bh[2], bh[3]);
                ldsm4(bl, bloB + jb);
                mma16816(acc[0][2*nt2],   ah0, bl[0], bl[1]);
                mma16816(acc[0][2*nt2+1], ah0, bl[2], bl[3]);
                mma16816(acc[1][2*nt2],   ah1, bl[0], bl[1]);
                mma16816(acc[1][2*nt2+1], ah1, bl[2], bl[3]);
            }
        }
    }

    // ---- softmax over j: single (max,sum) pair exchange ----
    {
        const int q2 = (lane & 3) * 2;
        float su2[4][2];
#pragma unroll
        for (int nt = 0; nt < 4; nt++) {
            float2 s2 = *(const float2*)(suS + jg*32 + nt*8 + q2);
            su2[nt][0] = s2.x; su2[nt][1] = s2.y;
        }
        const int rI = rbase + (lane >> 2);
        float mx[4];
#pragma unroll
        for (int rt = 0; rt < 2; rt++)
#pragma unroll
            for (int hf = 0; hf < 2; hf++) {
                float m = -1e30f;
#pragma unroll
                for (int nt = 0; nt < 4; nt++) {
                    float v0 = acc[rt][nt][2*hf]   + su2[nt][0];
                    float v1 = acc[rt][nt][2*hf+1] + su2[nt][1];
                    acc[rt][nt][2*hf] = v0; acc[rt][nt][2*hf+1] = v1;
                    m = fmaxf(m, fmaxf(v0, v1));
                }
                m = fmaxf(m, __shfl_xor_sync(0xffffffffu, m, 1));
                m = fmaxf(m, __shfl_xor_sync(0xffffffffu, m, 2));
                float s = 0.f;
#pragma unroll
                for (int nt = 0; nt < 4; nt++) {
                    float e0 = __expf(acc[rt][nt][2*hf]   - m);
                    float e1 = __expf(acc[rt][nt][2*hf+1] - m);
                    acc[rt][nt][2*hf] = e0; acc[rt][nt][2*hf+1] = e1;
                    s += e0 + e1;
                }
                s += __shfl_xor_sync(0xffffffffu, s, 1);
                s += __shfl_xor_sync(0xffffffffu, s, 2);
                int k = 2*rt + hf;
                mx[k] = m;
                if ((lane & 3) == 0) {
                    redM[jg*128 + rI + rt*16 + hf*8] = m;
                    redS[jg*128 + rI + rt*16 + hf*8] = s;
                }
            }
        __syncthreads();
#pragma unroll
        for (int rt = 0; rt < 2; rt++)
#pragma unroll
            for (int hf = 0; hf < 2; hf++) {
                int r = rI + rt*16 + hf*8;
                int k = 2*rt + hf;
                float m0 = redM[r],       m1 = redM[128 + r];
                float m2 = redM[256 + r], m3 = redM[384 + r];
                float m = fmaxf(fmaxf(m0, m1), fmaxf(m2, m3));
                float tot = redS[r]*__expf(m0 - m) + redS[128 + r]*__expf(m1 - m)
                          + redS[256 + r]*__expf(m2 - m) + redS[384 + r]*__expf(m3 - m);
                float f = __expf(mx[k] - m);
                if (jg == 0 && (lane & 3) == 0) {
                    invS[r] = 1.0f / tot;
                    Lsm[r]  = shS[r] + m;
                }
#pragma unroll
                for (int nt = 0; nt < 4; nt++) {
                    float e0 = acc[rt][nt][2*hf]   * f;
                    float e1 = acc[rt][nt][2*hf+1] * f;
                    uint32_t o = (uint32_t)r * HSTB + (uint32_t)(jg*32 + nt*8 + q2) * 2;
                    *(uint32_t*)(smem + AP_HI + o) = pk(e0, e1);
                    *(uint32_t*)(smem + AP_LO + o) = pk(rsd(e0), rsd(e1));
                }
            }
    }
    __syncthreads();

    // ---- GEMM2: two 32-d halves per warp (32 accumulators each) + epilogue ----
    {
        const uint32_t phi = sb + AP_HI + aoff + (uint32_t)rbase * HSTB;
        const uint32_t plo = sb + AP_LO + aoff + (uint32_t)rbase * HSTB;
        const int dg = jg;
        const int q2 = (lane & 3) * 2;
#pragma unroll 1
        for (int h2 = 0; h2 < 2; h2++) {
            float c2[2][4][4];
#pragma unroll
            for (int rt = 0; rt < 2; rt++)
#pragma unroll
                for (int nt = 0; nt < 4; nt++)
#pragma unroll
                    for (int c = 0; c < 4; c++) c2[rt][nt][c] = 0.f;

            const uint32_t thiB = sb + AU_HI + toff + (uint32_t)(dg*64 + h2*32) * 2;
            const uint32_t tloB = sb + AU_LO + toff + (uint32_t)(dg*64 + h2*32) * 2;
#pragma unroll 2
            for (int ksl = 0; ksl < 8; ksl++) {
                uint32_t ak = (uint32_t)ksl * 32;
                uint32_t jk = (uint32_t)ksl * 16 * USTB;
                uint32_t ah0[4], ah1[4], al0[4], al1[4];
                ldsm4(ah0, phi + ak);
                ldsm4(ah1, phi + ak + 16u*HSTB);
                ldsm4(al0, plo + ak);
                ldsm4(al1, plo + ak + 16u*HSTB);
#pragma unroll
                for (int nt2 = 0; nt2 < 2; nt2++) {
                    uint32_t dbo = jk + (uint32_t)nt2 * 32;
                    uint32_t bh[4], bl[4];
                    ldsm4t(bh, thiB + dbo);
                    mma16816(c2[0][2*nt2],   ah0, bh[0], bh[1]);
                    mma16816(c2[0][2*nt2+1], ah0, bh[2], bh[3]);
                    mma16816(c2[1][2*nt2],   ah1, bh[0], bh[1]);
                    mma16816(c2[1][2*nt2+1], ah1, bh[2], bh[3]);
                    mma16816(c2[0][2*nt2],   al0, bh[0], bh[1]);
                    mma16816(c2[0][2*nt2+1], al0, bh[2], bh[3]);
                    mma16816(c2[1][2*nt2],   al1, bh[0], bh[1]);
                    mma16816(c2[1][2*nt2+1], al1, bh[2], bh[3]);
                    ldsm4t(bl, tloB + dbo);
                    mma16816(c2[0][2*nt2],   ah0, bl[0], bl[1]);
                    mma16816(c2[0][2*nt2+1], ah0, bl[2], bl[3]);
                    mma16816(c2[1][2*nt2],   ah1, bl[0], bl[1]);
                    mma16816(c2[1][2*nt2+1], ah1, bl[2], bl[3]);
                }
            }
#pragma unroll
            for (int rt = 0; rt < 2; rt++)
#pragma unroll
                for (int hf = 0; hf < 2; hf++) {
                    int r = rbase + rt*16 + hf*8 + (lane >> 2);
                    float inv = invS[r];
                    size_t rowo = (size_t)(b*T_ + tb + r);
#pragma unroll
                    for (int nt = 0; nt < 4; nt++) {
                        int d = dg*64 + h2*32 + nt*8 + q2;
                        float2 hv = *(const float2*)(H + rowo*D_ + d);
                        float q0 = c2[rt][nt][2*hf]   * inv;
                        float q1 = c2[rt][nt][2*hf+1] * inv;
                        float* Gr = G + rowo*(4*D_) + d;
                        *(float2*)(Gr)          = hv;
                        *(float2*)(Gr + D_)     = make_float2(q0, q1);
                        *(float2*)(Gr + 2*D_)   = make_float2(hv.x*q0, hv.y*q1);
                    }
                }
        }
    }

    // ---- V-partial phase ----
    __syncthreads();   // U reads done; Lsm complete; AU area reusable
    {
        float lm = fmaxf(fmaxf(Lsm[lane], Lsm[lane+32]), fmaxf(Lsm[lane+64], Lsm[lane+96]));
#pragma unroll
        for (int o = 16; o; o >>= 1) lm = fmaxf(lm, __shfl_xor_sync(0xffffffffu, lm, o));

        float4 a0 = make_float4(0.f,0.f,0.f,0.f), a1 = make_float4(0.f,0.f,0.f,0.f);
        float sc = 0.f;
#pragma unroll
        for (int rr = 0; rr < 8; rr++) {
            int r = warp*8 + rr;
            float w = __expf(Lsm[r] - lm);
            const float4* Hr = (const float4*)(H + (size_t)(b*T_ + tb + r) * D_);
            float4 h0 = Hr[lane], h1 = Hr[lane + 32];
            a0.x = fmaf(w, h0.x, a0.x); a0.y = fmaf(w, h0.y, a0.y);
            a0.z = fmaf(w, h0.z, a0.z); a0.w = fmaf(w, h0.w, a0.w);
            a1.x = fmaf(w, h1.x, a1.x); a1.y = fmaf(w, h1.y, a1.y);
            a1.z = fmaf(w, h1.z, a1.z); a1.w = fmaf(w, h1.w, a1.w);
            sc += w;
        }
        float4* vred = (float4*)(smem + SM_VR + warp*1024);
        vred[lane]      = a0;
        vred[lane + 32] = a1;
        if (lane == 0) ((float*)(smem + SM_VS))[warp] = sc;
        __syncthreads();
        if (tid < D_) {
            const float* vr = (const float*)(smem + SM_VR);
            float v = 0.f;
#pragma unroll
            for (int w = 0; w < NWARP; w++) v += vr[w*256 + tid];
            g_Vp[((size_t)(b*8 + blockIdx.x))*D_ + tid] = v;
        }
        if (tid == 256) {
            const float* vs = (const float*)(smem + SM_VS);
            float st = 0.f;
#pragma unroll
            for (int w = 0; w < NWARP; w++) st += vs[w];
            g_Ms[(b*8 + blockIdx.x)*2]     = lm;
            g_Ms[(b*8 + blockIdx.x)*2 + 1] = st;
        }
    }

    // ---- finisher: last CTA of batch merges partials, writes G chunk 3 ----
    __threadfence();
    __syncthreads();
    if (tid == 0) finOld = atomicAdd(&g_cnt[b], 1u);
    __syncthreads();
    if (finOld == 7u) {
        float* q2cS = (float*)(smem + SM_Q2C);
        if (tid < D_) {
            float m = -1e30f;
#pragma unroll
            for (int c = 0; c < 8; c++) m = fmaxf(m, g_Ms[(b*8 + c)*2]);
            float ssum = 0.f, v = 0.f;
#pragma unroll
            for (int c = 0; c < 8; c++) {
                float f = __expf(g_Ms[(b*8 + c)*2] - m);
                ssum = fmaf(f, g_Ms[(b*8 + c)*2 + 1], ssum);
                v    = fmaf(f, g_Vp[((size_t)(b*8 + c))*D_ + tid], v);
            }
            q2cS[tid] = v / ssum;
        }
        if (tid == 0) g_cnt[b] = 0u;     // reset for next replay
        __syncthreads();
#pragma unroll 4
        for (int it = 0; it < (T_*D_/4)/512; it++) {
            int idx = it*512 + tid;
            int row = idx >> 6, d4 = idx & 63;
            size_t rowo = (size_t)(b*T_ + row);
            float4 h = ((const float4*)(H + rowo*D_))[d4];
            float4 q = ((const float4*)q2cS)[d4];
            ((float4*)(G + rowo*(4*D_) + 3*D_))[d4] =
                make_float4(h.x*q.x, h.y*q.y, h.z*q.z, h.w*q.w);
        }
    }
}

// ---------------------------------------------------------------------------
extern "C" void kernel_launch(void* const* d_in, const int* in_sizes, int n_in,
                              void* d_out, int out_size)
{
    const float* H   = (const float*)d_in[0];
    const float* U   = (const float*)d_in[1];
    const float* wh  = (const float*)d_in[2];
    const float* wu  = (const float*)d_in[3];
    const float* whu = (const float*)d_in[4];
    float* G = (float*)d_out;

    cudaFuncSetAttribute(bidaf_main, cudaFuncAttributeMaxDynamicSharedMemorySize, SMEM_TOTAL);

    dim3 g1(T_/TT, B_);
    bidaf_main<<<g1, 512, SMEM_TOTAL>>>(H, U, wh, wu, whu, G);
}

// round 16
// speedup vs baseline: 1.4855x; 1.4855x over previous
#include <cuda_runtime.h>
#include <cuda_bf16.h>
#include <stdint.h>

#define B_  64
#define T_  1024
#define J_  128
#define D_  256
#define TT  128
#define NWARP 16

// strides (bytes)
#define USTB 528     // U row stride: 132 words ≡ 4 mod 32 -> conflict-free ldmatrix
#define HSTB 272     // H/P row stride: 68 words ≡ 4 mod 32
#define CQS  260     // CQ row stride (floats)

// smem byte offsets
#define SM_SH   0
#define SM_SU   512
#define SM_INV  1024
#define SM_RM   1536                    // [4][128] f32 = 2048
#define SM_RS   3584                    // [4][128] f32 = 2048
#define SM_L    5632                    // L[128] f32 (ends 6144 < 8192)
#define AU_HI   8192
#define AU_LO   (AU_HI + J_*USTB)       // +67584
#define AH_HI   (AU_LO + J_*USTB)
#define AH_LO   (AH_HI + TT*HSTB)       // +34816
#define SMEM_TOTAL (AH_LO + TT*HSTB)    // 213504 B
#define AP_HI   AH_HI                   // P overlays H after GEMM1
#define AP_LO   AH_LO
#define SM_CQ   AU_HI                   // C2Q f32 [128][260] = 133120 (U dead after GEMM2)
#define SM_VR   AU_HI                   // V reduce [16][256] f32 = 16384 (CQ dead after G pass)
#define SM_VS   (AU_HI + 16384)         // s_c partials [16] f32
#define SM_Q2C  (AU_HI + 16448)         // q2c[256] f32 (finisher)

__device__ __align__(16) float g_Vp[B_*8*D_];   // per-tile V_c
__device__ __align__(16) float g_Ms[B_*8*2];    // per-tile {M_c, s_c}
__device__ unsigned g_cnt[B_];                  // finisher counters (self-resetting)

// ---------------- helpers ----------------
__device__ __forceinline__ uint32_t smem_u32(const void* p) {
    uint32_t a;
    asm("{ .reg .u64 t; cvta.to.shared.u64 t, %1; cvt.u32.u64 %0, t; }" : "=r"(a) : "l"(p));
    return a;
}
__device__ __forceinline__ void ldsm4(uint32_t* r, uint32_t addr) {
    asm volatile("ldmatrix.sync.aligned.m8n8.x4.shared.b16 {%0,%1,%2,%3}, [%4];"
        : "=r"(r[0]), "=r"(r[1]), "=r"(r[2]), "=r"(r[3]) : "r"(addr));
}
__device__ __forceinline__ void ldsm4t(uint32_t* r, uint32_t addr) {
    asm volatile("ldmatrix.sync.aligned.m8n8.x4.trans.shared.b16 {%0,%1,%2,%3}, [%4];"
        : "=r"(r[0]), "=r"(r[1]), "=r"(r[2]), "=r"(r[3]) : "r"(addr));
}
__device__ __forceinline__ void mma16816(float* c, const uint32_t* a, uint32_t b0, uint32_t b1) {
    asm volatile("mma.sync.aligned.m16n8k16.row.col.f32.bf16.bf16.f32 "
        "{%0,%1,%2,%3}, {%4,%5,%6,%7}, {%8,%9}, {%0,%1,%2,%3};"
        : "+f"(c[0]), "+f"(c[1]), "+f"(c[2]), "+f"(c[3])
        : "r"(a[0]), "r"(a[1]), "r"(a[2]), "r"(a[3]), "r"(b0), "r"(b1));
}
static __device__ __forceinline__ uint32_t pk(float a, float b) {
    return (uint32_t)__bfloat16_as_ushort(__float2bfloat16(a))
         | ((uint32_t)__bfloat16_as_ushort(__float2bfloat16(b)) << 16);
}
static __device__ __forceinline__ float rsd(float x) {
    return x - __bfloat162float(__float2bfloat16(x));
}

// ---------------------------------------------------------------------------
// Single fused kernel. 1 CTA per (b, 128-row t-tile). 16 warps.
// ---------------------------------------------------------------------------
__global__ void __launch_bounds__(512, 1)
bidaf_main(const float* __restrict__ H, const float* __restrict__ U,
           const float* __restrict__ w_h, const float* __restrict__ w_u,
           const float* __restrict__ w_hu, float* __restrict__ G)
{
    extern __shared__ char smem[];
    const uint32_t sb = smem_u32(smem);
    float* shS  = (float*)(smem + SM_SH);
    float* suS  = (float*)(smem + SM_SU);
    float* invS = (float*)(smem + SM_INV);
    float* redM = (float*)(smem + SM_RM);
    float* redS = (float*)(smem + SM_RS);
    float* Lsm  = (float*)(smem + SM_L);
    __shared__ unsigned finOld;

    const int tid  = threadIdx.x;
    const int lane = tid & 31;
    const int warp = tid >> 5;
    const int rg   = warp & 3;
    const int jg   = warp >> 2;       // 0..3 (also dg in GEMM2)
    const int rbase = rg * 32;
    const int b    = blockIdx.y;
    const int tb   = blockIdx.x * TT;

    const int lr = lane & 7;
    const int g  = lane >> 3;
    const uint32_t aoff = (uint32_t)((((g & 1) << 3) + lr) * HSTB + ((g >> 1) << 4));
    const uint32_t boff = (uint32_t)((((g >> 1) << 3) + lr) * USTB + ((g & 1) << 4));
    const uint32_t toff = (uint32_t)((((g & 1) << 3) + lr) * USTB + ((g >> 1) << 4));

    // ---- stage U full-K (hi/lo) + su ----
    {
        const float4* wu4 = (const float4*)w_u;
        float4 wa = wu4[lane], wb = wu4[32 + lane];
#pragma unroll
        for (int it = 0; it < 8; it++) {
            int j = warp + it * NWARP;
            const float4* Uj = (const float4*)(U + (size_t)(b * J_ + j) * D_);
            float4 v0 = Uj[lane], v1 = Uj[32 + lane];
            float s = v0.x*wa.x + v0.y*wa.y + v0.z*wa.z + v0.w*wa.w
                    + v1.x*wb.x + v1.y*wb.y + v1.z*wb.z + v1.w*wb.w;
#pragma unroll
            for (int o = 16; o; o >>= 1) s += __shfl_xor_sync(0xffffffffu, s, o);
            if (lane == 0) suS[j] = s;
            uint32_t ro = (uint32_t)j * USTB + (uint32_t)lane * 8;
            *(uint2*)(smem + AU_HI + ro)       = make_uint2(pk(v0.x,v0.y), pk(v0.z,v0.w));
            *(uint2*)(smem + AU_HI + ro + 256) = make_uint2(pk(v1.x,v1.y), pk(v1.z,v1.w));
            *(uint2*)(smem + AU_LO + ro)       = make_uint2(pk(rsd(v0.x),rsd(v0.y)), pk(rsd(v0.z),rsd(v0.w)));
            *(uint2*)(smem + AU_LO + ro + 256) = make_uint2(pk(rsd(v1.x),rsd(v1.y)), pk(rsd(v1.z),rsd(v1.w)));
        }
    }

    float acc[2][4][4];
#pragma unroll
    for (int rt = 0; rt < 2; rt++)
#pragma unroll
        for (int nt = 0; nt < 4; nt++)
#pragma unroll
            for (int c = 0; c < 4; c++) acc[rt][nt][c] = 0.f;

    // ---- GEMM1 over two H k-chunks (32 j per warp) ----
    const uint32_t ahi = sb + AH_HI + aoff + (uint32_t)rbase * HSTB;
    const uint32_t alo = sb + AH_LO + aoff + (uint32_t)rbase * HSTB;
    for (int kc = 0; kc < 2; kc++) {
        if (kc == 1) __syncthreads();
        {
            const float4* wh4  = (const float4*)w_h;
            const float4* whu4 = (const float4*)w_hu;
            float4 wv = wh4[kc*32 + lane];
            float4 mv = whu4[kc*32 + lane];
#pragma unroll
            for (int it = 0; it < 8; it++) {
                int row = warp + it * NWARP;
                float4 v = ((const float4*)(H + (size_t)(b*T_ + tb + row) * D_ + kc*128))[lane];
                float s = v.x*wv.x + v.y*wv.y + v.z*wv.z + v.w*wv.w;
#pragma unroll
                for (int o = 16; o; o >>= 1) s += __shfl_xor_sync(0xffffffffu, s, o);
                if (lane == 0) { if (kc == 0) shS[row] = s; else shS[row] += s; }
                float x0 = v.x*mv.x, x1 = v.y*mv.y, x2 = v.z*mv.z, x3 = v.w*mv.w;
                uint32_t ro = (uint32_t)row * HSTB + (uint32_t)lane * 8;
                *(uint2*)(smem + AH_HI + ro) = make_uint2(pk(x0,x1), pk(x2,x3));
                *(uint2*)(smem + AH_LO + ro) = make_uint2(pk(rsd(x0),rsd(x1)), pk(rsd(x2),rsd(x3)));
            }
        }
        __syncthreads();

        const uint32_t bhiB = sb + AU_HI + boff + (uint32_t)(kc * 256);
        const uint32_t bloB = sb + AU_LO + boff + (uint32_t)(kc * 256);
#pragma unroll 2
        for (int ksl = 0; ksl < 8; ksl++) {
            uint32_t ak = (uint32_t)ksl * 32;
            uint32_t ah0[4], ah1[4], al0[4], al1[4];
            ldsm4(ah0, ahi + ak);
            ldsm4(ah1, ahi + ak + 16u*HSTB);
            ldsm4(al0, alo + ak);
            ldsm4(al1, alo + ak + 16u*HSTB);
#pragma unroll
            for (int nt2 = 0; nt2 < 2; nt2++) {
                uint32_t jb = (uint32_t)(jg*32 + nt2*16) * USTB + ak;
                uint32_t bh[4], bl[4];
                ldsm4(bh, bhiB + jb);
                mma16816(acc[0][2*nt2],   ah0, bh[0], bh[1]);
                mma16816(acc[0][2*nt2+1], ah0, bh[2], bh[3]);
                mma16816(acc[1][2*nt2],   ah1, bh[0], bh[1]);
                mma16816(acc[1][2*nt2+1], ah1, bh[2], bh[3]);
                mma16816(acc[0][2*nt2],   al0, bh[0], bh[1]);
                mma16816(acc[0][2*nt2+1], al0, bh[2], bh[3]);
                mma16816(acc[1][2*nt2],   al1, bh[0], bh[1]);
                mma16816(acc[1][2*nt2+1], al1, bh[2], bh[3]);
                ldsm4(bl, bloB + jb);
                mma16816(acc[0][2*nt2],   ah0, bl[0], bl[1]);
                mma16816(acc[0][2*nt2+1], ah0, bl[2], bl[3]);
                mma16816(acc[1][2*nt2],   ah1, bl[0], bl[1]);
                mma16816(acc[1][2*nt2+1], ah1, bl[2], bl[3]);
            }
        }
    }

    // ---- softmax over j: single (max,sum) pair exchange ----
    {
        const int q2 = (lane & 3) * 2;
        float su2[4][2];
#pragma unroll
        for (int nt = 0; nt < 4; nt++) {
            float2 s2 = *(const float2*)(suS + jg*32 + nt*8 + q2);
            su2[nt][0] = s2.x; su2[nt][1] = s2.y;
        }
        const int rI = rbase + (lane >> 2);
        float mx[4];
#pragma unroll
        for (int rt = 0; rt < 2; rt++)
#pragma unroll
            for (int hf = 0; hf < 2; hf++) {
                float m = -1e30f;
#pragma unroll
                for (int nt = 0; nt < 4; nt++) {
                    float v0 = acc[rt][nt][2*hf]   + su2[nt][0];
                    float v1 = acc[rt][nt][2*hf+1] + su2[nt][1];
                    acc[rt][nt][2*hf] = v0; acc[rt][nt][2*hf+1] = v1;
                    m = fmaxf(m, fmaxf(v0, v1));
                }
                m = fmaxf(m, __shfl_xor_sync(0xffffffffu, m, 1));
                m = fmaxf(m, __shfl_xor_sync(0xffffffffu, m, 2));
                float s = 0.f;
#pragma unroll
                for (int nt = 0; nt < 4; nt++) {
                    float e0 = __expf(acc[rt][nt][2*hf]   - m);
                    float e1 = __expf(acc[rt][nt][2*hf+1] - m);
                    acc[rt][nt][2*hf] = e0; acc[rt][nt][2*hf+1] = e1;
                    s += e0 + e1;
                }
                s += __shfl_xor_sync(0xffffffffu, s, 1);
                s += __shfl_xor_sync(0xffffffffu, s, 2);
                int k = 2*rt + hf;
                mx[k] = m;
                if ((lane & 3) == 0) {
                    redM[jg*128 + rI + rt*16 + hf*8] = m;
                    redS[jg*128 + rI + rt*16 + hf*8] = s;
                }
            }
        __syncthreads();
#pragma unroll
        for (int rt = 0; rt < 2; rt++)
#pragma unroll
            for (int hf = 0; hf < 2; hf++) {
                int r = rI + rt*16 + hf*8;
                int k = 2*rt + hf;
                float m0 = redM[r],       m1 = redM[128 + r];
                float m2 = redM[256 + r], m3 = redM[384 + r];
                float m = fmaxf(fmaxf(m0, m1), fmaxf(m2, m3));
                float tot = redS[r]*__expf(m0 - m) + redS[128 + r]*__expf(m1 - m)
                          + redS[256 + r]*__expf(m2 - m) + redS[384 + r]*__expf(m3 - m);
                float f = __expf(mx[k] - m);
                if (jg == 0 && (lane & 3) == 0) {
                    invS[r] = 1.0f / tot;
                    Lsm[r]  = shS[r] + m;
                }
#pragma unroll
                for (int nt = 0; nt < 4; nt++) {
                    float e0 = acc[rt][nt][2*hf]   * f;
                    float e1 = acc[rt][nt][2*hf+1] * f;
                    uint32_t o = (uint32_t)r * HSTB + (uint32_t)(jg*32 + nt*8 + q2) * 2;
                    *(uint32_t*)(smem + AP_HI + o) = pk(e0, e1);
                    *(uint32_t*)(smem + AP_LO + o) = pk(rsd(e0), rsd(e1));
                }
            }
    }
    __syncthreads();

    // ---- GEMM2 (64 d per warp) ----
    float c2[2][8][4];
    {
        const uint32_t phi = sb + AP_HI + aoff + (uint32_t)rbase * HSTB;
        const uint32_t plo = sb + AP_LO + aoff + (uint32_t)rbase * HSTB;
        const int dg = jg;
#pragma unroll
        for (int rt = 0; rt < 2; rt++)
#pragma unroll
            for (int nt = 0; nt < 8; nt++)
#pragma unroll
                for (int c = 0; c < 4; c++) c2[rt][nt][c] = 0.f;

        const uint32_t thiB = sb + AU_HI + toff + (uint32_t)(dg*64) * 2;
        const uint32_t tloB = sb + AU_LO + toff + (uint32_t)(dg*64) * 2;
#pragma unroll 2
        for (int ksl = 0; ksl < 8; ksl++) {
            uint32_t ak = (uint32_t)ksl * 32;
            uint32_t jk = (uint32_t)ksl * 16 * USTB;
            uint32_t ah0[4], ah1[4], al0[4], al1[4];
            ldsm4(ah0, phi + ak);
            ldsm4(ah1, phi + ak + 16u*HSTB);
            ldsm4(al0, plo + ak);
            ldsm4(al1, plo + ak + 16u*HSTB);
#pragma unroll
            for (int nt2 = 0; nt2 < 4; nt2++) {
                uint32_t dbo = jk + (uint32_t)(nt2*16) * 2;
                uint32_t bh[4], bl[4];
                ldsm4t(bh, thiB + dbo);
                mma16816(c2[0][2*nt2],   ah0, bh[0], bh[1]);
                mma16816(c2[0][2*nt2+1], ah0, bh[2], bh[3]);
                mma16816(c2[1][2*nt2],   ah1, bh[0], bh[1]);
                mma16816(c2[1][2*nt2+1], ah1, bh[2], bh[3]);
                mma16816(c2[0][2*nt2],   al0, bh[0], bh[1]);
                mma16816(c2[0][2*nt2+1], al0, bh[2], bh[3]);
                mma16816(c2[1][2*nt2],   al1, bh[0], bh[1]);
                mma16816(c2[1][2*nt2+1], al1, bh[2], bh[3]);
                ldsm4t(bl, tloB + dbo);
                mma16816(c2[0][2*nt2],   ah0, bl[0], bl[1]);
                mma16816(c2[0][2*nt2+1], ah0, bl[2], bl[3]);
                mma16816(c2[1][2*nt2],   ah1, bl[0], bl[1]);
                mma16816(c2[1][2*nt2+1], ah1, bl[2], bl[3]);
            }
        }
    }

    // ---- epilogue: C2Q -> smem (normalized), then coalesced float4 G writes ----
    __syncthreads();   // all warps done reading U/P smem before CQ overlay
    {
        float* CQ = (float*)(smem + SM_CQ);
        const int q2 = (lane & 3) * 2;
        const int dg = jg;
#pragma unroll
        for (int rt = 0; rt < 2; rt++)
#pragma unroll
            for (int hf = 0; hf < 2; hf++) {
                int r = rbase + rt*16 + hf*8 + (lane >> 2);
                float inv = invS[r];
#pragma unroll
                for (int nt = 0; nt < 8; nt++) {
                    int d = dg*64 + nt*8 + q2;
                    *(float2*)(CQ + r*CQS + d) =
                        make_float2(c2[rt][nt][2*hf] * inv, c2[rt][nt][2*hf+1] * inv);
                }
            }
    }
    __syncthreads();
    {
        const float* CQ = (const float*)(smem + SM_CQ);
#pragma unroll
        for (int it = 0; it < 16; it++) {
            int idx = it*512 + tid;
            int row = idx >> 6, c4 = idx & 63;
            size_t rowo = (size_t)(b*T_ + tb + row);
            float4 h = ((const float4*)(H + rowo*D_))[c4];
            float4 q = *(const float4*)(CQ + row*CQS + c4*4);
            float4* Gr = (float4*)(G + rowo*(4*D_));
            Gr[c4]        = h;
            Gr[64 + c4]   = q;
            Gr[128 + c4]  = make_float4(h.x*q.x, h.y*q.y, h.z*q.z, h.w*q.w);
        }
    }

    // ---- V-partial phase ----
    __syncthreads();   // CQ reads done; Lsm complete; VR area reusable
    {
        float lm = fmaxf(fmaxf(Lsm[lane], Lsm[lane+32]), fmaxf(Lsm[lane+64], Lsm[lane+96]));
#pragma unroll
        for (int o = 16; o; o >>= 1) lm = fmaxf(lm, __shfl_xor_sync(0xffffffffu, lm, o));

        float4 a0 = make_float4(0.f,0.f,0.f,0.f), a1 = make_float4(0.f,0.f,0.f,0.f);
        float sc = 0.f;
#pragma unroll
        for (int rr = 0; rr < 8; rr++) {
            int r = warp*8 + rr;
            float w = __expf(Lsm[r] - lm);
            const float4* Hr = (const float4*)(H + (size_t)(b*T_ + tb + r) * D_);
            float4 h0 = Hr[lane], h1 = Hr[lane + 32];
            a0.x = fmaf(w, h0.x, a0.x); a0.y = fmaf(w, h0.y, a0.y);
            a0.z = fmaf(w, h0.z, a0.z); a0.w = fmaf(w, h0.w, a0.w);
            a1.x = fmaf(w, h1.x, a1.x); a1.y = fmaf(w, h1.y, a1.y);
            a1.z = fmaf(w, h1.z, a1.z); a1.w = fmaf(w, h1.w, a1.w);
            sc += w;
        }
        float4* vred = (float4*)(smem + SM_VR + warp*1024);
        vred[lane]      = a0;
        vred[lane + 32] = a1;
        if (lane == 0) ((float*)(smem + SM_VS))[warp] = sc;
        __syncthreads();
        if (tid < D_) {
            const float* vr = (const float*)(smem + SM_VR);
            float v = 0.f;
#pragma unroll
            for (int w = 0; w < NWARP; w++) v += vr[w*256 + tid];
            g_Vp[((size_t)(b*8 + blockIdx.x))*D_ + tid] = v;
        }
        if (tid == 256) {
            const float* vs = (const float*)(smem + SM_VS);
            float st = 0.f;
#pragma unroll
            for (int w = 0; w < NWARP; w++) st += vs[w];
            g_Ms[(b*8 + blockIdx.x)*2]     = lm;
            g_Ms[(b*8 + blockIdx.x)*2 + 1] = st;
        }
    }

    // ---- finisher: last CTA of batch merges partials, writes G chunk 3 ----
    __threadfence();
    __syncthreads();
    if (tid == 0) finOld = atomicAdd(&g_cnt[b], 1u);
    __syncthreads();
    if (finOld == 7u) {
        float* q2cS = (float*)(smem + SM_Q2C);
        if (tid < D_) {
            float m = -1e30f;
#pragma unroll
            for (int c = 0; c < 8; c++) m = fmaxf(m, g_Ms[(b*8 + c)*2]);
            float ssum = 0.f, v = 0.f;
#pragma unroll
            for (int c = 0; c < 8; c++) {
                float f = __expf(g_Ms[(b*8 + c)*2] - m);
                ssum = fmaf(f, g_Ms[(b*8 + c)*2 + 1], ssum);
                v    = fmaf(f, g_Vp[((size_t)(b*8 + c))*D_ + tid], v);
            }
            q2cS[tid] = v / ssum;
        }
        if (tid == 0) g_cnt[b] = 0u;     // reset for next replay
        __syncthreads();
#pragma unroll 4
        for (int it = 0; it < (T_*D_/4)/512; it++) {
            int idx = it*512 + tid;
            int row = idx >> 6, d4 = idx & 63;
            size_t rowo = (size_t)(b*T_ + row);
            float4 h = ((const float4*)(H + rowo*D_))[d4];
            float4 q = ((const float4*)q2cS)[d4];
            ((float4*)(G + rowo*(4*D_) + 3*D_))[d4] =
                make_float4(h.x*q.x, h.y*q.y, h.z*q.z, h.w*q.w);
        }
    }
}

// ---------------------------------------------------------------------------
extern "C" void kernel_launch(void* const* d_in, const int* in_sizes, int n_in,
                              void* d_out, int out_size)
{
    const float* H   = (const float*)d_in[0];
    const float* U   = (const float*)d_in[1];
    const float* wh  = (const float*)d_in[2];
    const float* wu  = (const float*)d_in[3];
    const float* whu = (const float*)d_in[4];
    float* G = (float*)d_out;

    cudaFuncSetAttribute(bidaf_main, cudaFuncAttributeMaxDynamicSharedMemorySize, SMEM_TOTAL);

    dim3 g1(T_/TT, B_);
    bidaf_main<<<g1, 512, SMEM_TOTAL>>>(H, U, wh, wu, whu, G);
}